// round 6
// baseline (speedup 1.0000x reference)
#include <cuda_runtime.h>
#include <cuda_bf16.h>
#include <cstdint>

// ---------------------------------------------------------------------------
// SpatialAttention on GB300 (sm_103, mma.sync HMMA path)
//   K1 : qkv_hi/lo = x @ W_qkv + b_qkv   (split-bf16 mma GEMM, bf16 hi/lo out)
//   K2 : flash attention (cp.async bf16 tiles, frag softmax, hi/lo out)
//   K3 : out = attn @ W_proj + b_proj    (split-bf16 mma GEMM, fp32 out)
// Round 6: gemm warp tile 64x32 -> 64x64 (8 warps/CTA): LDSM per MMA drops
// 0.5 -> 0.167, un-saturating the smem fragment path that capped tensor at 48%.
// ---------------------------------------------------------------------------

#define BT_TOTAL 16
#define NTOK     1024
#define DMODEL   512
#define NHEADS   8
#define HD       64
#define MROWS    (BT_TOTAL * NTOK)      // 16384
#define QKV_COLS (3 * DMODEL)           // 1536
#define KDIM     512

__device__ __nv_bfloat16  g_qkvh[(size_t)MROWS * QKV_COLS];
__device__ __nv_bfloat16  g_qkvl[(size_t)MROWS * QKV_COLS];
__device__ __nv_bfloat16  g_x_hi[(size_t)MROWS * DMODEL];
__device__ __nv_bfloat16  g_x_lo[(size_t)MROWS * DMODEL];
__device__ __nv_bfloat16  g_wqt_hi[(size_t)QKV_COLS * DMODEL];
__device__ __nv_bfloat16  g_wqt_lo[(size_t)QKV_COLS * DMODEL];
__device__ __nv_bfloat16  g_wpt_hi[(size_t)DMODEL * DMODEL];
__device__ __nv_bfloat16  g_wpt_lo[(size_t)DMODEL * DMODEL];
__device__ __nv_bfloat16  g_attn_hi[(size_t)MROWS * DMODEL];
__device__ __nv_bfloat16  g_attn_lo[(size_t)MROWS * DMODEL];

// ---------------------------------------------------------------------------
// helpers
// ---------------------------------------------------------------------------
__device__ __forceinline__ uint32_t smem_u32(const void* p) {
    uint32_t a;
    asm("{ .reg .u64 t; cvta.to.shared.u64 t, %1; cvt.u32.u64 %0, t; }"
        : "=r"(a) : "l"(p));
    return a;
}
__device__ __forceinline__ void ldsm4(uint32_t* r, uint32_t a) {
    asm volatile("ldmatrix.sync.aligned.m8n8.x4.shared.b16 {%0,%1,%2,%3}, [%4];"
        : "=r"(r[0]), "=r"(r[1]), "=r"(r[2]), "=r"(r[3]) : "r"(a));
}
__device__ __forceinline__ void ldsm4t(uint32_t* r, uint32_t a) {
    asm volatile("ldmatrix.sync.aligned.m8n8.x4.trans.shared.b16 {%0,%1,%2,%3}, [%4];"
        : "=r"(r[0]), "=r"(r[1]), "=r"(r[2]), "=r"(r[3]) : "r"(a));
}
__device__ __forceinline__ void mma16816(float* d, const uint32_t* a, const uint32_t* b) {
    asm volatile("mma.sync.aligned.m16n8k16.row.col.f32.bf16.bf16.f32 "
        "{%0,%1,%2,%3},{%4,%5,%6,%7},{%8,%9},{%0,%1,%2,%3};"
        : "+f"(d[0]), "+f"(d[1]), "+f"(d[2]), "+f"(d[3])
        : "r"(a[0]), "r"(a[1]), "r"(a[2]), "r"(a[3]), "r"(b[0]), "r"(b[1]));
}
__device__ __forceinline__ void cp_async16(uint32_t s, const void* g) {
    asm volatile("cp.async.cg.shared.global [%0], [%1], 16;" :: "r"(s), "l"(g));
}
#define CP_COMMIT() asm volatile("cp.async.commit_group;")
#define CP_WAIT(n)  asm volatile("cp.async.wait_group %0;" :: "n"(n) : "memory")

__device__ __forceinline__ void hilo2(float a, float b, uint32_t& h, uint32_t& l) {
    __nv_bfloat162 hb = __floats2bfloat162_rn(a, b);
    float2 hf = __bfloat1622float2(hb);
    __nv_bfloat162 lb = __floats2bfloat162_rn(a - hf.x, b - hf.y);
    h = *(uint32_t*)&hb;
    l = *(uint32_t*)&lb;
}

// ---------------------------------------------------------------------------
// prep kernels
// ---------------------------------------------------------------------------
__global__ void cvt_hilo(const float* __restrict__ X, __nv_bfloat16* __restrict__ H,
                         __nv_bfloat16* __restrict__ L, int n4)
{
    int i = blockIdx.x * blockDim.x + threadIdx.x;
    if (i >= n4) return;
    float4 v = ((const float4*)X)[i];
    uint32_t h0, l0, h1, l1;
    hilo2(v.x, v.y, h0, l0);
    hilo2(v.z, v.w, h1, l1);
    ((uint32_t*)H)[i * 2 + 0] = h0;
    ((uint32_t*)H)[i * 2 + 1] = h1;
    ((uint32_t*)L)[i * 2 + 0] = l0;
    ((uint32_t*)L)[i * 2 + 1] = l1;
}

__global__ void transpose_cvt(const float* __restrict__ W, __nv_bfloat16* __restrict__ Th,
                              __nv_bfloat16* __restrict__ Tl, int K, int N)
{
    __shared__ float tile[32][33];
    const int bx = blockIdx.x * 32;
    const int by = blockIdx.y * 32;
    const int tx = threadIdx.x, ty = threadIdx.y;
    #pragma unroll
    for (int i = 0; i < 32; i += 8)
        tile[ty + i][tx] = W[(size_t)(by + ty + i) * N + bx + tx];
    __syncthreads();
    #pragma unroll
    for (int i = 0; i < 32; i += 8) {
        float v = tile[tx][ty + i];
        size_t o = (size_t)(bx + ty + i) * K + by + tx;
        __nv_bfloat16 h = __float2bfloat16(v);
        Th[o] = h;
        Tl[o] = __float2bfloat16(v - __bfloat162float(h));
    }
}

// ---------------------------------------------------------------------------
// split-bf16 GEMM: CTA 128x256, 256 threads (8 warps 2x4, warp tile 64x64),
// k-chunk 32, 3-stage cp.async pipeline. 80B-padded rows (LDSM conflict-free).
// Per k16 step per warp: 16 LDSM feed 96 MMAs (3 split passes of 32).
// ---------------------------------------------------------------------------
#define GROWB 80
#define G_A   (128 * GROWB)
#define G_B   (256 * GROWB)
#define GSTG  (2 * G_A + 2 * G_B)
#define GEMM_SMEM (3 * GSTG)

__global__ __launch_bounds__(256, 1)
void gemm_mma(const __nv_bfloat16* __restrict__ Ah, const __nv_bfloat16* __restrict__ Al,
              const __nv_bfloat16* __restrict__ Bh, const __nv_bfloat16* __restrict__ Bl,
              const float* __restrict__ bias, float* __restrict__ Cf,
              __nv_bfloat16* __restrict__ Chi, __nv_bfloat16* __restrict__ Clo, int Ntot)
{
    extern __shared__ char sm[];
    const uint32_t sb = smem_u32(sm);
    const int t = threadIdx.x, lane = t & 31, w = t >> 5;
    const int wm = w >> 2, wn = w & 3;          // 2 x 4 warps
    const int bm = blockIdx.y * 128, bn = blockIdx.x * 256;

    // loader tasks: A 512 (2/thread), B 1024 (4/thread)
    const __nv_bfloat16* pAh_[2];
    const __nv_bfloat16* pAl_[2];
    uint32_t adst_[2];
    #pragma unroll
    for (int i = 0; i < 2; ++i) {
        const int idx = t + i * 256;
        const int row = idx >> 2, blk = idx & 3;
        pAh_[i] = Ah + (size_t)(bm + row) * KDIM + blk * 8;
        pAl_[i] = Al + (size_t)(bm + row) * KDIM + blk * 8;
        adst_[i] = (uint32_t)(row * GROWB + blk * 16);
    }
    const __nv_bfloat16* pBh_[4];
    const __nv_bfloat16* pBl_[4];
    uint32_t bdst_[4];
    #pragma unroll
    for (int i = 0; i < 4; ++i) {
        const int idx = t + i * 256;
        const int row = idx >> 2, blk = idx & 3;
        pBh_[i] = Bh + (size_t)(bn + row) * KDIM + blk * 8;
        pBl_[i] = Bl + (size_t)(bn + row) * KDIM + blk * 8;
        bdst_[i] = (uint32_t)(row * GROWB + blk * 16);
    }

    float acc[4][8][4];
    #pragma unroll
    for (int a = 0; a < 4; ++a)
        #pragma unroll
        for (int b = 0; b < 8; ++b)
            #pragma unroll
            for (int c = 0; c < 4; ++c) acc[a][b][c] = 0.f;

    #pragma unroll
    for (int c = 0; c < 2; ++c) {
        const int koff = c * 32;
        const uint32_t st = sb + c * GSTG;
        #pragma unroll
        for (int i = 0; i < 2; ++i) {
            cp_async16(st + adst_[i],       pAh_[i] + koff);
            cp_async16(st + G_A + adst_[i], pAl_[i] + koff);
        }
        #pragma unroll
        for (int i = 0; i < 4; ++i) {
            cp_async16(st + 2 * G_A + bdst_[i],       pBh_[i] + koff);
            cp_async16(st + 2 * G_A + G_B + bdst_[i], pBl_[i] + koff);
        }
        CP_COMMIT();
    }

    int stg = 0;
    for (int c = 0; c < 16; ++c) {
        if (c < 14) CP_WAIT(1); else CP_WAIT(0);
        __syncthreads();

        if (c + 2 < 16) {
            const int koff = (c + 2) * 32;
            const int s2 = (stg + 2 == 3) ? 0 : ((stg + 2 == 4) ? 1 : stg + 2);
            const uint32_t st = sb + s2 * GSTG;
            #pragma unroll
            for (int i = 0; i < 2; ++i) {
                cp_async16(st + adst_[i],       pAh_[i] + koff);
                cp_async16(st + G_A + adst_[i], pAl_[i] + koff);
            }
            #pragma unroll
            for (int i = 0; i < 4; ++i) {
                cp_async16(st + 2 * G_A + bdst_[i],       pBh_[i] + koff);
                cp_async16(st + 2 * G_A + G_B + bdst_[i], pBl_[i] + koff);
            }
            CP_COMMIT();
        }

        const uint32_t aH = sb + stg * GSTG;
        const uint32_t aL = aH + G_A;
        const uint32_t bH = aH + 2 * G_A;
        const uint32_t bL = bH + G_B;

        #pragma unroll
        for (int ks = 0; ks < 2; ++ks) {
            const uint32_t blkA = 2 * ks + (lane >> 4);
            const uint32_t blkB = 2 * ks + ((lane >> 3) & 1);
            const uint32_t rbase = wm * 64 + ((lane >> 3) & 1) * 8 + (lane & 7);
            const uint32_t nbase = wn * 64 + (lane >> 4) * 8 + (lane & 7);

            uint32_t bh[4][4], bl[4][4], ah[4][4];
            #pragma unroll
            for (int j = 0; j < 4; ++j) {
                const uint32_t off = (nbase + j * 16) * GROWB + blkB * 16;
                ldsm4(bh[j], bH + off);
                ldsm4(bl[j], bL + off);
            }
            #pragma unroll
            for (int mf = 0; mf < 4; ++mf)
                ldsm4(ah[mf], aH + (rbase + mf * 16) * GROWB + blkA * 16);

            // pass 1: hi*hi (32 independent MMAs)
            #pragma unroll
            for (int mf = 0; mf < 4; ++mf)
                #pragma unroll
                for (int nf = 0; nf < 8; ++nf)
                    mma16816(acc[mf][nf], ah[mf], &bh[nf >> 1][(nf & 1) * 2]);
            // pass 2: hi*lo
            #pragma unroll
            for (int mf = 0; mf < 4; ++mf)
                #pragma unroll
                for (int nf = 0; nf < 8; ++nf)
                    mma16816(acc[mf][nf], ah[mf], &bl[nf >> 1][(nf & 1) * 2]);
            // pass 3: lo*hi (al streamed per mf)
            #pragma unroll
            for (int mf = 0; mf < 4; ++mf) {
                uint32_t al[4];
                ldsm4(al, aL + (rbase + mf * 16) * GROWB + blkA * 16);
                #pragma unroll
                for (int nf = 0; nf < 8; ++nf)
                    mma16816(acc[mf][nf], al, &bh[nf >> 1][(nf & 1) * 2]);
            }
        }
        stg = (stg == 2) ? 0 : stg + 1;
    }

    const int g = lane >> 2, q2 = (lane & 3) * 2;
    #pragma unroll
    for (int mf = 0; mf < 4; ++mf) {
        const int r0 = bm + wm * 64 + mf * 16 + g;
        #pragma unroll
        for (int nf = 0; nf < 8; ++nf) {
            const int col = bn + wn * 64 + nf * 8 + q2;
            const float b0 = bias[col], b1 = bias[col + 1];
            const float v00 = acc[mf][nf][0] + b0, v01 = acc[mf][nf][1] + b1;
            const float v10 = acc[mf][nf][2] + b0, v11 = acc[mf][nf][3] + b1;
            if (Chi) {
                uint32_t hh, ll;
                hilo2(v00, v01, hh, ll);
                *(uint32_t*)&Chi[(size_t)r0 * Ntot + col] = hh;
                *(uint32_t*)&Clo[(size_t)r0 * Ntot + col] = ll;
                hilo2(v10, v11, hh, ll);
                *(uint32_t*)&Chi[(size_t)(r0 + 8) * Ntot + col] = hh;
                *(uint32_t*)&Clo[(size_t)(r0 + 8) * Ntot + col] = ll;
            } else {
                *(float2*)&Cf[(size_t)r0 * Ntot + col]       = make_float2(v00, v01);
                *(float2*)&Cf[(size_t)(r0 + 8) * Ntot + col] = make_float2(v10, v11);
            }
        }
    }
}

// ---------------------------------------------------------------------------
// Flash attention (unchanged from round 5): bf16 hi/lo cp.async, double-
// buffered KV, fragment softmax, pass-separated MMA triples.
// ---------------------------------------------------------------------------
#define FQ_H 0
#define FQ_L 16384
#define FKV0 32768
#define FKV_STG 32768
#define FLASH_SMEM 98304

__global__ __launch_bounds__(256, 2)
void flash_mma()
{
    const int rb = blockIdx.x;
    const int pp = blockIdx.y;
    const int bt = pp >> 3, h = pp & 7;
    extern __shared__ char sm[];
    const uint32_t sb = smem_u32(sm);
    const int t = threadIdx.x, lane = t & 31, w = t >> 5;
    const size_t base = (size_t)bt * NTOK * QKV_COLS;

    const int lrow0 = t >> 3,         lblk0 = t & 7;
    const int lrow1 = (t + 256) >> 3, lblk1 = (t + 256) & 7;
    const uint32_t kvd0 = (uint32_t)(lrow0 * 128 + ((lblk0 ^ (lrow0 & 7)) * 16));
    const uint32_t kvd1 = (uint32_t)(lrow1 * 128 + ((lblk1 ^ (lrow1 & 7)) * 16));

    {
        #pragma unroll
        for (int i = 0; i < 4; ++i) {
            const int idx = t + i * 256;
            const int row = idx >> 3, blk = idx & 7;
            const uint32_t d = (uint32_t)(row * 128 + ((blk ^ (row & 7)) * 16));
            const size_t src = base + (size_t)(rb * 128 + row) * QKV_COLS + h * HD + blk * 8;
            cp_async16(sb + FQ_H + d, g_qkvh + src);
            cp_async16(sb + FQ_L + d, g_qkvl + src);
        }
        const size_t k0 = base + (size_t)lrow0 * QKV_COLS + DMODEL + h * HD + lblk0 * 8;
        const size_t k1 = base + (size_t)lrow1 * QKV_COLS + DMODEL + h * HD + lblk1 * 8;
        const uint32_t st = sb + FKV0;
        cp_async16(st + kvd0,         g_qkvh + k0);
        cp_async16(st + kvd1,         g_qkvh + k1);
        cp_async16(st + 8192 + kvd0,  g_qkvl + k0);
        cp_async16(st + 8192 + kvd1,  g_qkvl + k1);
        cp_async16(st + 16384 + kvd0, g_qkvh + k0 + DMODEL);
        cp_async16(st + 16384 + kvd1, g_qkvh + k1 + DMODEL);
        cp_async16(st + 24576 + kvd0, g_qkvl + k0 + DMODEL);
        cp_async16(st + 24576 + kvd1, g_qkvl + k1 + DMODEL);
        CP_COMMIT();
    }

    float s_m0 = -1e30f, s_m1 = -1e30f, s_l0 = 0.f, s_l1 = 0.f;
    float o[8][4];
    #pragma unroll
    for (int nf = 0; nf < 8; ++nf)
        #pragma unroll
        for (int i = 0; i < 4; ++i) o[nf][i] = 0.f;

    const int g = lane >> 2, q2 = (lane & 3) * 2;
    const float SC = 0.125f;

    for (int kb = 0; kb < 16; ++kb) {
        CP_WAIT(0);
        __syncthreads();

        if (kb + 1 < 16) {
            const int r = (kb + 1) * 64;
            const size_t k0 = base + (size_t)(r + lrow0) * QKV_COLS + DMODEL + h * HD + lblk0 * 8;
            const size_t k1 = base + (size_t)(r + lrow1) * QKV_COLS + DMODEL + h * HD + lblk1 * 8;
            const uint32_t st = sb + FKV0 + ((kb + 1) & 1) * FKV_STG;
            cp_async16(st + kvd0,         g_qkvh + k0);
            cp_async16(st + kvd1,         g_qkvh + k1);
            cp_async16(st + 8192 + kvd0,  g_qkvl + k0);
            cp_async16(st + 8192 + kvd1,  g_qkvl + k1);
            cp_async16(st + 16384 + kvd0, g_qkvh + k0 + DMODEL);
            cp_async16(st + 16384 + kvd1, g_qkvh + k1 + DMODEL);
            cp_async16(st + 24576 + kvd0, g_qkvl + k0 + DMODEL);
            cp_async16(st + 24576 + kvd1, g_qkvl + k1 + DMODEL);
            CP_COMMIT();
        }

        const uint32_t kH = sb + FKV0 + (kb & 1) * FKV_STG;
        const uint32_t kL = kH + 8192;
        const uint32_t vH = kH + 16384;
        const uint32_t vL = kH + 24576;

        float s[8][4];
        #pragma unroll
        for (int nf = 0; nf < 8; ++nf)
            #pragma unroll
            for (int i = 0; i < 4; ++i) s[nf][i] = 0.f;

        #pragma unroll
        for (int ks = 0; ks < 4; ++ks) {
            uint32_t ah[4], al[4];
            {
                const uint32_t r   = w * 16 + ((lane >> 3) & 1) * 8 + (lane & 7);
                const uint32_t blk = 2 * ks + (lane >> 4);
                const uint32_t off = r * 128 + ((blk ^ (r & 7)) * 16);
                ldsm4(ah, sb + FQ_H + off);
                ldsm4(al, sb + FQ_L + off);
            }
            #pragma unroll
            for (int j = 0; j < 4; j += 2) {
                uint32_t bh[2][4], bl[2][4];
                #pragma unroll
                for (int u = 0; u < 2; ++u) {
                    const uint32_t key = (j + u) * 16 + (lane >> 4) * 8 + (lane & 7);
                    const uint32_t blk = 2 * ks + ((lane >> 3) & 1);
                    const uint32_t off = key * 128 + ((blk ^ (key & 7)) * 16);
                    ldsm4(bh[u], kH + off);
                    ldsm4(bl[u], kL + off);
                }
                mma16816(s[2 * j],     ah, &bh[0][0]);
                mma16816(s[2 * j + 1], ah, &bh[0][2]);
                mma16816(s[2 * j + 2], ah, &bh[1][0]);
                mma16816(s[2 * j + 3], ah, &bh[1][2]);
                mma16816(s[2 * j],     ah, &bl[0][0]);
                mma16816(s[2 * j + 1], ah, &bl[0][2]);
                mma16816(s[2 * j + 2], ah, &bl[1][0]);
                mma16816(s[2 * j + 3], ah, &bl[1][2]);
                mma16816(s[2 * j],     al, &bh[0][0]);
                mma16816(s[2 * j + 1], al, &bh[0][2]);
                mma16816(s[2 * j + 2], al, &bh[1][0]);
                mma16816(s[2 * j + 3], al, &bh[1][2]);
            }
        }

        float mt0 = -1e30f, mt1 = -1e30f;
        #pragma unroll
        for (int nf = 0; nf < 8; ++nf) {
            mt0 = fmaxf(mt0, fmaxf(s[nf][0], s[nf][1]));
            mt1 = fmaxf(mt1, fmaxf(s[nf][2], s[nf][3]));
        }
        mt0 = fmaxf(mt0, __shfl_xor_sync(0xffffffffu, mt0, 1));
        mt0 = fmaxf(mt0, __shfl_xor_sync(0xffffffffu, mt0, 2));
        mt1 = fmaxf(mt1, __shfl_xor_sync(0xffffffffu, mt1, 1));
        mt1 = fmaxf(mt1, __shfl_xor_sync(0xffffffffu, mt1, 2));

        const float mn0 = fmaxf(s_m0, mt0), mn1 = fmaxf(s_m1, mt1);
        const float c0 = __expf((s_m0 - mn0) * SC), c1 = __expf((s_m1 - mn1) * SC);
        s_m0 = mn0; s_m1 = mn1;
        const float mo0 = mn0 * SC, mo1 = mn1 * SC;

        float ps0 = 0.f, ps1 = 0.f;
        #pragma unroll
        for (int nf = 0; nf < 8; ++nf) {
            s[nf][0] = __expf(fmaf(s[nf][0], SC, -mo0));
            s[nf][1] = __expf(fmaf(s[nf][1], SC, -mo0));
            s[nf][2] = __expf(fmaf(s[nf][2], SC, -mo1));
            s[nf][3] = __expf(fmaf(s[nf][3], SC, -mo1));
            ps0 += s[nf][0] + s[nf][1];
            ps1 += s[nf][2] + s[nf][3];
        }
        ps0 += __shfl_xor_sync(0xffffffffu, ps0, 1);
        ps0 += __shfl_xor_sync(0xffffffffu, ps0, 2);
        ps1 += __shfl_xor_sync(0xffffffffu, ps1, 1);
        ps1 += __shfl_xor_sync(0xffffffffu, ps1, 2);
        s_l0 = s_l0 * c0 + ps0;
        s_l1 = s_l1 * c1 + ps1;

        #pragma unroll
        for (int nf = 0; nf < 8; ++nf) {
            o[nf][0] *= c0; o[nf][1] *= c0;
            o[nf][2] *= c1; o[nf][3] *= c1;
        }

        #pragma unroll
        for (int ks = 0; ks < 4; ++ks) {
            uint32_t ph[4], pl[4];
            hilo2(s[2 * ks][0],     s[2 * ks][1],     ph[0], pl[0]);
            hilo2(s[2 * ks][2],     s[2 * ks][3],     ph[1], pl[1]);
            hilo2(s[2 * ks + 1][0], s[2 * ks + 1][1], ph[2], pl[2]);
            hilo2(s[2 * ks + 1][2], s[2 * ks + 1][3], ph[3], pl[3]);
            #pragma unroll
            for (int j = 0; j < 4; j += 2) {
                uint32_t vh[2][4], vl[2][4];
                #pragma unroll
                for (int u = 0; u < 2; ++u) {
                    const uint32_t key = ks * 16 + ((lane >> 3) & 1) * 8 + (lane & 7);
                    const uint32_t blk = 2 * (j + u) + (lane >> 4);
                    const uint32_t off = key * 128 + ((blk ^ (key & 7)) * 16);
                    ldsm4t(vh[u], vH + off);
                    ldsm4t(vl[u], vL + off);
                }
                mma16816(o[2 * j],     ph, &vh[0][0]);
                mma16816(o[2 * j + 1], ph, &vh[0][2]);
                mma16816(o[2 * j + 2], ph, &vh[1][0]);
                mma16816(o[2 * j + 3], ph, &vh[1][2]);
                mma16816(o[2 * j],     ph, &vl[0][0]);
                mma16816(o[2 * j + 1], ph, &vl[0][2]);
                mma16816(o[2 * j + 2], ph, &vl[1][0]);
                mma16816(o[2 * j + 3], ph, &vl[1][2]);
                mma16816(o[2 * j],     pl, &vh[0][0]);
                mma16816(o[2 * j + 1], pl, &vh[0][2]);
                mma16816(o[2 * j + 2], pl, &vh[1][0]);
                mma16816(o[2 * j + 3], pl, &vh[1][2]);
            }
        }
    }

    const float inv0 = 1.0f / s_l0, inv1 = 1.0f / s_l1;
    const size_t row0 = (size_t)bt * NTOK + rb * 128 + w * 16 + g;
    const size_t row1 = row0 + 8;
    #pragma unroll
    for (int nf = 0; nf < 8; ++nf) {
        const int col = h * HD + nf * 8 + q2;
        uint32_t hh, ll;
        hilo2(o[nf][0] * inv0, o[nf][1] * inv0, hh, ll);
        *(uint32_t*)&g_attn_hi[row0 * DMODEL + col] = hh;
        *(uint32_t*)&g_attn_lo[row0 * DMODEL + col] = ll;
        hilo2(o[nf][2] * inv1, o[nf][3] * inv1, hh, ll);
        *(uint32_t*)&g_attn_hi[row1 * DMODEL + col] = hh;
        *(uint32_t*)&g_attn_lo[row1 * DMODEL + col] = ll;
    }
}

// ---------------------------------------------------------------------------
extern "C" void kernel_launch(void* const* d_in, const int* in_sizes, int n_in,
                              void* d_out, int out_size)
{
    const float* x      = (const float*)d_in[0];
    const float* W_qkv  = (const float*)d_in[1];
    const float* b_qkv  = (const float*)d_in[2];
    const float* W_proj = (const float*)d_in[3];
    const float* b_proj = (const float*)d_in[4];
    float* out = (float*)d_out;

    void *pqh, *pql, *pxh, *pxl, *pwqh, *pwql, *pwph, *pwpl, *pah, *pal;
    cudaGetSymbolAddress(&pqh, g_qkvh);    cudaGetSymbolAddress(&pql, g_qkvl);
    cudaGetSymbolAddress(&pxh, g_x_hi);    cudaGetSymbolAddress(&pxl, g_x_lo);
    cudaGetSymbolAddress(&pwqh, g_wqt_hi); cudaGetSymbolAddress(&pwql, g_wqt_lo);
    cudaGetSymbolAddress(&pwph, g_wpt_hi); cudaGetSymbolAddress(&pwpl, g_wpt_lo);
    cudaGetSymbolAddress(&pah, g_attn_hi); cudaGetSymbolAddress(&pal, g_attn_lo);

    cudaFuncSetAttribute(gemm_mma,
                         cudaFuncAttributeMaxDynamicSharedMemorySize, GEMM_SMEM);
    cudaFuncSetAttribute(flash_mma,
                         cudaFuncAttributeMaxDynamicSharedMemorySize, FLASH_SMEM);

    {
        const int n4 = MROWS * DMODEL / 4;
        cvt_hilo<<<(n4 + 255) / 256, 256>>>(x, (__nv_bfloat16*)pxh,
                                            (__nv_bfloat16*)pxl, n4);
    }
    {
        dim3 blk(32, 8);
        transpose_cvt<<<dim3(QKV_COLS / 32, DMODEL / 32), blk>>>(
            W_qkv, (__nv_bfloat16*)pwqh, (__nv_bfloat16*)pwql, DMODEL, QKV_COLS);
        transpose_cvt<<<dim3(DMODEL / 32, DMODEL / 32), blk>>>(
            W_proj, (__nv_bfloat16*)pwph, (__nv_bfloat16*)pwpl, DMODEL, DMODEL);
    }
    {
        dim3 grid(QKV_COLS / 256, MROWS / 128);
        gemm_mma<<<grid, 256, GEMM_SMEM>>>(
            (const __nv_bfloat16*)pxh, (const __nv_bfloat16*)pxl,
            (const __nv_bfloat16*)pwqh, (const __nv_bfloat16*)pwql,
            b_qkv, nullptr,
            (__nv_bfloat16*)pqh, (__nv_bfloat16*)pql, QKV_COLS);
    }
    {
        dim3 grid(NTOK / 128, BT_TOTAL * NHEADS);
        flash_mma<<<grid, 256, FLASH_SMEM>>>();
    }
    {
        dim3 grid(DMODEL / 256, MROWS / 128);
        gemm_mma<<<grid, 256, GEMM_SMEM>>>(
            (const __nv_bfloat16*)pah, (const __nv_bfloat16*)pal,
            (const __nv_bfloat16*)pwph, (const __nv_bfloat16*)pwpl,
            b_proj, out, nullptr, nullptr, DMODEL);
    }
}

// round 7
// speedup vs baseline: 1.0780x; 1.0780x over previous
#include <cuda_runtime.h>
#include <cuda_bf16.h>
#include <cstdint>

// ---------------------------------------------------------------------------
// SpatialAttention on GB300 (sm_103, mma.sync HMMA path)
// Round 7: gemm CTA 128x128, 2-stage pipeline, 80KB smem -> 2 CTAs/SM so the
// co-resident CTA fills per-chunk wait/barrier bubbles (flash evidence: 2
// CTAs/SM -> 74% tensor vs gemm's 47% at 1 CTA/SM).
// ---------------------------------------------------------------------------

#define BT_TOTAL 16
#define NTOK     1024
#define DMODEL   512
#define NHEADS   8
#define HD       64
#define MROWS    (BT_TOTAL * NTOK)      // 16384
#define QKV_COLS (3 * DMODEL)           // 1536
#define KDIM     512

__device__ __nv_bfloat16  g_qkvh[(size_t)MROWS * QKV_COLS];
__device__ __nv_bfloat16  g_qkvl[(size_t)MROWS * QKV_COLS];
__device__ __nv_bfloat16  g_x_hi[(size_t)MROWS * DMODEL];
__device__ __nv_bfloat16  g_x_lo[(size_t)MROWS * DMODEL];
__device__ __nv_bfloat16  g_wqt_hi[(size_t)QKV_COLS * DMODEL];
__device__ __nv_bfloat16  g_wqt_lo[(size_t)QKV_COLS * DMODEL];
__device__ __nv_bfloat16  g_wpt_hi[(size_t)DMODEL * DMODEL];
__device__ __nv_bfloat16  g_wpt_lo[(size_t)DMODEL * DMODEL];
__device__ __nv_bfloat16  g_attn_hi[(size_t)MROWS * DMODEL];
__device__ __nv_bfloat16  g_attn_lo[(size_t)MROWS * DMODEL];

// ---------------------------------------------------------------------------
// helpers
// ---------------------------------------------------------------------------
__device__ __forceinline__ uint32_t smem_u32(const void* p) {
    uint32_t a;
    asm("{ .reg .u64 t; cvta.to.shared.u64 t, %1; cvt.u32.u64 %0, t; }"
        : "=r"(a) : "l"(p));
    return a;
}
__device__ __forceinline__ void ldsm4(uint32_t* r, uint32_t a) {
    asm volatile("ldmatrix.sync.aligned.m8n8.x4.shared.b16 {%0,%1,%2,%3}, [%4];"
        : "=r"(r[0]), "=r"(r[1]), "=r"(r[2]), "=r"(r[3]) : "r"(a));
}
__device__ __forceinline__ void ldsm4t(uint32_t* r, uint32_t a) {
    asm volatile("ldmatrix.sync.aligned.m8n8.x4.trans.shared.b16 {%0,%1,%2,%3}, [%4];"
        : "=r"(r[0]), "=r"(r[1]), "=r"(r[2]), "=r"(r[3]) : "r"(a));
}
__device__ __forceinline__ void mma16816(float* d, const uint32_t* a, const uint32_t* b) {
    asm volatile("mma.sync.aligned.m16n8k16.row.col.f32.bf16.bf16.f32 "
        "{%0,%1,%2,%3},{%4,%5,%6,%7},{%8,%9},{%0,%1,%2,%3};"
        : "+f"(d[0]), "+f"(d[1]), "+f"(d[2]), "+f"(d[3])
        : "r"(a[0]), "r"(a[1]), "r"(a[2]), "r"(a[3]), "r"(b[0]), "r"(b[1]));
}
__device__ __forceinline__ void cp_async16(uint32_t s, const void* g) {
    asm volatile("cp.async.cg.shared.global [%0], [%1], 16;" :: "r"(s), "l"(g));
}
#define CP_COMMIT() asm volatile("cp.async.commit_group;")
#define CP_WAIT(n)  asm volatile("cp.async.wait_group %0;" :: "n"(n) : "memory")

__device__ __forceinline__ void hilo2(float a, float b, uint32_t& h, uint32_t& l) {
    __nv_bfloat162 hb = __floats2bfloat162_rn(a, b);
    float2 hf = __bfloat1622float2(hb);
    __nv_bfloat162 lb = __floats2bfloat162_rn(a - hf.x, b - hf.y);
    h = *(uint32_t*)&hb;
    l = *(uint32_t*)&lb;
}

// ---------------------------------------------------------------------------
// prep kernels
// ---------------------------------------------------------------------------
__global__ void cvt_hilo(const float* __restrict__ X, __nv_bfloat16* __restrict__ H,
                         __nv_bfloat16* __restrict__ L, int n4)
{
    int i = blockIdx.x * blockDim.x + threadIdx.x;
    if (i >= n4) return;
    float4 v = ((const float4*)X)[i];
    uint32_t h0, l0, h1, l1;
    hilo2(v.x, v.y, h0, l0);
    hilo2(v.z, v.w, h1, l1);
    ((uint32_t*)H)[i * 2 + 0] = h0;
    ((uint32_t*)H)[i * 2 + 1] = h1;
    ((uint32_t*)L)[i * 2 + 0] = l0;
    ((uint32_t*)L)[i * 2 + 1] = l1;
}

__global__ void transpose_cvt(const float* __restrict__ W, __nv_bfloat16* __restrict__ Th,
                              __nv_bfloat16* __restrict__ Tl, int K, int N)
{
    __shared__ float tile[32][33];
    const int bx = blockIdx.x * 32;
    const int by = blockIdx.y * 32;
    const int tx = threadIdx.x, ty = threadIdx.y;
    #pragma unroll
    for (int i = 0; i < 32; i += 8)
        tile[ty + i][tx] = W[(size_t)(by + ty + i) * N + bx + tx];
    __syncthreads();
    #pragma unroll
    for (int i = 0; i < 32; i += 8) {
        float v = tile[tx][ty + i];
        size_t o = (size_t)(bx + ty + i) * K + by + tx;
        __nv_bfloat16 h = __float2bfloat16(v);
        Th[o] = h;
        Tl[o] = __float2bfloat16(v - __bfloat162float(h));
    }
}

// ---------------------------------------------------------------------------
// split-bf16 GEMM: CTA 128x128, 256 threads (8 warps 2x4, warp tile 64x32),
// k-chunk 32, 2-stage cp.async double buffer, 80KB smem => 2 CTAs/SM.
// 80B-padded rows: (5r+b) mod 8 permutation -> LDSM conflict-free.
// ---------------------------------------------------------------------------
#define GROWB 80
#define G_T   (128 * GROWB)             // 10240 per matrix per stage
#define GSTG  (4 * G_T)                 // Ah, Al, Bh, Bl = 40960
#define GEMM_SMEM (2 * GSTG)            // 81920

__global__ __launch_bounds__(256, 2)
void gemm_mma(const __nv_bfloat16* __restrict__ Ah, const __nv_bfloat16* __restrict__ Al,
              const __nv_bfloat16* __restrict__ Bh, const __nv_bfloat16* __restrict__ Bl,
              const float* __restrict__ bias, float* __restrict__ Cf,
              __nv_bfloat16* __restrict__ Chi, __nv_bfloat16* __restrict__ Clo, int Ntot)
{
    extern __shared__ char sm[];
    const uint32_t sb = smem_u32(sm);
    const int t = threadIdx.x, lane = t & 31, w = t >> 5;
    const int wm = w >> 2, wn = w & 3;          // 2 x 4 warps
    const int bm = blockIdx.y * 128, bn = blockIdx.x * 128;

    // loaders: A and B each 512 tasks (128 rows x 4 16B-blocks), 2/thread
    const __nv_bfloat16* pA_[2][2];   // [i][hi/lo]
    const __nv_bfloat16* pB_[2][2];
    uint32_t dst_[2];
    #pragma unroll
    for (int i = 0; i < 2; ++i) {
        const int idx = t + i * 256;
        const int row = idx >> 2, blk = idx & 3;
        pA_[i][0] = Ah + (size_t)(bm + row) * KDIM + blk * 8;
        pA_[i][1] = Al + (size_t)(bm + row) * KDIM + blk * 8;
        pB_[i][0] = Bh + (size_t)(bn + row) * KDIM + blk * 8;
        pB_[i][1] = Bl + (size_t)(bn + row) * KDIM + blk * 8;
        dst_[i] = (uint32_t)(row * GROWB + blk * 16);
    }

    float acc[4][4][4];
    #pragma unroll
    for (int a = 0; a < 4; ++a)
        #pragma unroll
        for (int b = 0; b < 4; ++b)
            #pragma unroll
            for (int c = 0; c < 4; ++c) acc[a][b][c] = 0.f;

    // prologue: chunk 0 -> stage 0
    #pragma unroll
    for (int i = 0; i < 2; ++i) {
        cp_async16(sb + dst_[i],           pA_[i][0]);
        cp_async16(sb + G_T + dst_[i],     pA_[i][1]);
        cp_async16(sb + 2 * G_T + dst_[i], pB_[i][0]);
        cp_async16(sb + 3 * G_T + dst_[i], pB_[i][1]);
    }
    CP_COMMIT();

    for (int c = 0; c < 16; ++c) {
        CP_WAIT(0);
        __syncthreads();

        if (c + 1 < 16) {   // prefetch next chunk into other stage
            const int koff = (c + 1) * 32;
            const uint32_t st = sb + ((c + 1) & 1) * GSTG;
            #pragma unroll
            for (int i = 0; i < 2; ++i) {
                cp_async16(st + dst_[i],           pA_[i][0] + koff);
                cp_async16(st + G_T + dst_[i],     pA_[i][1] + koff);
                cp_async16(st + 2 * G_T + dst_[i], pB_[i][0] + koff);
                cp_async16(st + 3 * G_T + dst_[i], pB_[i][1] + koff);
            }
            CP_COMMIT();
        }

        const uint32_t aH = sb + (c & 1) * GSTG;
        const uint32_t aL = aH + G_T;
        const uint32_t bH = aH + 2 * G_T;
        const uint32_t bL = aH + 3 * G_T;

        #pragma unroll
        for (int ks = 0; ks < 2; ++ks) {
            uint32_t bh[2][4], bl[2][4];
            #pragma unroll
            for (int j = 0; j < 2; ++j) {
                const uint32_t n   = wn * 32 + j * 16 + (lane >> 4) * 8 + (lane & 7);
                const uint32_t blk = 2 * ks + ((lane >> 3) & 1);
                ldsm4(bh[j], bH + n * GROWB + blk * 16);
                ldsm4(bl[j], bL + n * GROWB + blk * 16);
            }
            uint32_t ah[4][4];
            const uint32_t rbase = wm * 64 + ((lane >> 3) & 1) * 8 + (lane & 7);
            const uint32_t ablk2 = 2 * ks + (lane >> 4);
            #pragma unroll
            for (int mf = 0; mf < 4; ++mf)
                ldsm4(ah[mf], aH + (rbase + mf * 16) * GROWB + ablk2 * 16);

            // pass 1: hi*hi
            #pragma unroll
            for (int mf = 0; mf < 4; ++mf)
                #pragma unroll
                for (int nf = 0; nf < 4; ++nf)
                    mma16816(acc[mf][nf], ah[mf], &bh[nf >> 1][(nf & 1) * 2]);
            // pass 2: hi*lo
            #pragma unroll
            for (int mf = 0; mf < 4; ++mf)
                #pragma unroll
                for (int nf = 0; nf < 4; ++nf)
                    mma16816(acc[mf][nf], ah[mf], &bl[nf >> 1][(nf & 1) * 2]);
            // pass 3: lo*hi
            #pragma unroll
            for (int mf = 0; mf < 4; ++mf) {
                uint32_t al[4];
                ldsm4(al, aL + (rbase + mf * 16) * GROWB + ablk2 * 16);
                #pragma unroll
                for (int nf = 0; nf < 4; ++nf)
                    mma16816(acc[mf][nf], al, &bh[nf >> 1][(nf & 1) * 2]);
            }
        }
    }

    const int g = lane >> 2, q2 = (lane & 3) * 2;
    #pragma unroll
    for (int mf = 0; mf < 4; ++mf) {
        const int r0 = bm + wm * 64 + mf * 16 + g;
        #pragma unroll
        for (int nf = 0; nf < 4; ++nf) {
            const int col = bn + wn * 32 + nf * 8 + q2;
            const float b0 = bias[col], b1 = bias[col + 1];
            const float v00 = acc[mf][nf][0] + b0, v01 = acc[mf][nf][1] + b1;
            const float v10 = acc[mf][nf][2] + b0, v11 = acc[mf][nf][3] + b1;
            if (Chi) {
                uint32_t hh, ll;
                hilo2(v00, v01, hh, ll);
                *(uint32_t*)&Chi[(size_t)r0 * Ntot + col] = hh;
                *(uint32_t*)&Clo[(size_t)r0 * Ntot + col] = ll;
                hilo2(v10, v11, hh, ll);
                *(uint32_t*)&Chi[(size_t)(r0 + 8) * Ntot + col] = hh;
                *(uint32_t*)&Clo[(size_t)(r0 + 8) * Ntot + col] = ll;
            } else {
                *(float2*)&Cf[(size_t)r0 * Ntot + col]       = make_float2(v00, v01);
                *(float2*)&Cf[(size_t)(r0 + 8) * Ntot + col] = make_float2(v10, v11);
            }
        }
    }
}

// ---------------------------------------------------------------------------
// Flash attention (unchanged): bf16 hi/lo cp.async, double-buffered KV,
// fragment softmax, pass-separated MMA triples. 2 CTAs/SM.
// ---------------------------------------------------------------------------
#define FQ_H 0
#define FQ_L 16384
#define FKV0 32768
#define FKV_STG 32768
#define FLASH_SMEM 98304

__global__ __launch_bounds__(256, 2)
void flash_mma()
{
    const int rb = blockIdx.x;
    const int pp = blockIdx.y;
    const int bt = pp >> 3, h = pp & 7;
    extern __shared__ char sm[];
    const uint32_t sb = smem_u32(sm);
    const int t = threadIdx.x, lane = t & 31, w = t >> 5;
    const size_t base = (size_t)bt * NTOK * QKV_COLS;

    const int lrow0 = t >> 3,         lblk0 = t & 7;
    const int lrow1 = (t + 256) >> 3, lblk1 = (t + 256) & 7;
    const uint32_t kvd0 = (uint32_t)(lrow0 * 128 + ((lblk0 ^ (lrow0 & 7)) * 16));
    const uint32_t kvd1 = (uint32_t)(lrow1 * 128 + ((lblk1 ^ (lrow1 & 7)) * 16));

    {
        #pragma unroll
        for (int i = 0; i < 4; ++i) {
            const int idx = t + i * 256;
            const int row = idx >> 3, blk = idx & 7;
            const uint32_t d = (uint32_t)(row * 128 + ((blk ^ (row & 7)) * 16));
            const size_t src = base + (size_t)(rb * 128 + row) * QKV_COLS + h * HD + blk * 8;
            cp_async16(sb + FQ_H + d, g_qkvh + src);
            cp_async16(sb + FQ_L + d, g_qkvl + src);
        }
        const size_t k0 = base + (size_t)lrow0 * QKV_COLS + DMODEL + h * HD + lblk0 * 8;
        const size_t k1 = base + (size_t)lrow1 * QKV_COLS + DMODEL + h * HD + lblk1 * 8;
        const uint32_t st = sb + FKV0;
        cp_async16(st + kvd0,         g_qkvh + k0);
        cp_async16(st + kvd1,         g_qkvh + k1);
        cp_async16(st + 8192 + kvd0,  g_qkvl + k0);
        cp_async16(st + 8192 + kvd1,  g_qkvl + k1);
        cp_async16(st + 16384 + kvd0, g_qkvh + k0 + DMODEL);
        cp_async16(st + 16384 + kvd1, g_qkvh + k1 + DMODEL);
        cp_async16(st + 24576 + kvd0, g_qkvl + k0 + DMODEL);
        cp_async16(st + 24576 + kvd1, g_qkvl + k1 + DMODEL);
        CP_COMMIT();
    }

    float s_m0 = -1e30f, s_m1 = -1e30f, s_l0 = 0.f, s_l1 = 0.f;
    float o[8][4];
    #pragma unroll
    for (int nf = 0; nf < 8; ++nf)
        #pragma unroll
        for (int i = 0; i < 4; ++i) o[nf][i] = 0.f;

    const int g = lane >> 2, q2 = (lane & 3) * 2;
    const float SC = 0.125f;

    for (int kb = 0; kb < 16; ++kb) {
        CP_WAIT(0);
        __syncthreads();

        if (kb + 1 < 16) {
            const int r = (kb + 1) * 64;
            const size_t k0 = base + (size_t)(r + lrow0) * QKV_COLS + DMODEL + h * HD + lblk0 * 8;
            const size_t k1 = base + (size_t)(r + lrow1) * QKV_COLS + DMODEL + h * HD + lblk1 * 8;
            const uint32_t st = sb + FKV0 + ((kb + 1) & 1) * FKV_STG;
            cp_async16(st + kvd0,         g_qkvh + k0);
            cp_async16(st + kvd1,         g_qkvh + k1);
            cp_async16(st + 8192 + kvd0,  g_qkvl + k0);
            cp_async16(st + 8192 + kvd1,  g_qkvl + k1);
            cp_async16(st + 16384 + kvd0, g_qkvh + k0 + DMODEL);
            cp_async16(st + 16384 + kvd1, g_qkvh + k1 + DMODEL);
            cp_async16(st + 24576 + kvd0, g_qkvl + k0 + DMODEL);
            cp_async16(st + 24576 + kvd1, g_qkvl + k1 + DMODEL);
            CP_COMMIT();
        }

        const uint32_t kH = sb + FKV0 + (kb & 1) * FKV_STG;
        const uint32_t kL = kH + 8192;
        const uint32_t vH = kH + 16384;
        const uint32_t vL = kH + 24576;

        float s[8][4];
        #pragma unroll
        for (int nf = 0; nf < 8; ++nf)
            #pragma unroll
            for (int i = 0; i < 4; ++i) s[nf][i] = 0.f;

        #pragma unroll
        for (int ks = 0; ks < 4; ++ks) {
            uint32_t ah[4], al[4];
            {
                const uint32_t r   = w * 16 + ((lane >> 3) & 1) * 8 + (lane & 7);
                const uint32_t blk = 2 * ks + (lane >> 4);
                const uint32_t off = r * 128 + ((blk ^ (r & 7)) * 16);
                ldsm4(ah, sb + FQ_H + off);
                ldsm4(al, sb + FQ_L + off);
            }
            #pragma unroll
            for (int j = 0; j < 4; j += 2) {
                uint32_t bh[2][4], bl[2][4];
                #pragma unroll
                for (int u = 0; u < 2; ++u) {
                    const uint32_t key = (j + u) * 16 + (lane >> 4) * 8 + (lane & 7);
                    const uint32_t blk = 2 * ks + ((lane >> 3) & 1);
                    const uint32_t off = key * 128 + ((blk ^ (key & 7)) * 16);
                    ldsm4(bh[u], kH + off);
                    ldsm4(bl[u], kL + off);
                }
                mma16816(s[2 * j],     ah, &bh[0][0]);
                mma16816(s[2 * j + 1], ah, &bh[0][2]);
                mma16816(s[2 * j + 2], ah, &bh[1][0]);
                mma16816(s[2 * j + 3], ah, &bh[1][2]);
                mma16816(s[2 * j],     ah, &bl[0][0]);
                mma16816(s[2 * j + 1], ah, &bl[0][2]);
                mma16816(s[2 * j + 2], ah, &bl[1][0]);
                mma16816(s[2 * j + 3], ah, &bl[1][2]);
                mma16816(s[2 * j],     al, &bh[0][0]);
                mma16816(s[2 * j + 1], al, &bh[0][2]);
                mma16816(s[2 * j + 2], al, &bh[1][0]);
                mma16816(s[2 * j + 3], al, &bh[1][2]);
            }
        }

        float mt0 = -1e30f, mt1 = -1e30f;
        #pragma unroll
        for (int nf = 0; nf < 8; ++nf) {
            mt0 = fmaxf(mt0, fmaxf(s[nf][0], s[nf][1]));
            mt1 = fmaxf(mt1, fmaxf(s[nf][2], s[nf][3]));
        }
        mt0 = fmaxf(mt0, __shfl_xor_sync(0xffffffffu, mt0, 1));
        mt0 = fmaxf(mt0, __shfl_xor_sync(0xffffffffu, mt0, 2));
        mt1 = fmaxf(mt1, __shfl_xor_sync(0xffffffffu, mt1, 1));
        mt1 = fmaxf(mt1, __shfl_xor_sync(0xffffffffu, mt1, 2));

        const float mn0 = fmaxf(s_m0, mt0), mn1 = fmaxf(s_m1, mt1);
        const float c0 = __expf((s_m0 - mn0) * SC), c1 = __expf((s_m1 - mn1) * SC);
        s_m0 = mn0; s_m1 = mn1;
        const float mo0 = mn0 * SC, mo1 = mn1 * SC;

        float ps0 = 0.f, ps1 = 0.f;
        #pragma unroll
        for (int nf = 0; nf < 8; ++nf) {
            s[nf][0] = __expf(fmaf(s[nf][0], SC, -mo0));
            s[nf][1] = __expf(fmaf(s[nf][1], SC, -mo0));
            s[nf][2] = __expf(fmaf(s[nf][2], SC, -mo1));
            s[nf][3] = __expf(fmaf(s[nf][3], SC, -mo1));
            ps0 += s[nf][0] + s[nf][1];
            ps1 += s[nf][2] + s[nf][3];
        }
        ps0 += __shfl_xor_sync(0xffffffffu, ps0, 1);
        ps0 += __shfl_xor_sync(0xffffffffu, ps0, 2);
        ps1 += __shfl_xor_sync(0xffffffffu, ps1, 1);
        ps1 += __shfl_xor_sync(0xffffffffu, ps1, 2);
        s_l0 = s_l0 * c0 + ps0;
        s_l1 = s_l1 * c1 + ps1;

        #pragma unroll
        for (int nf = 0; nf < 8; ++nf) {
            o[nf][0] *= c0; o[nf][1] *= c0;
            o[nf][2] *= c1; o[nf][3] *= c1;
        }

        #pragma unroll
        for (int ks = 0; ks < 4; ++ks) {
            uint32_t ph[4], pl[4];
            hilo2(s[2 * ks][0],     s[2 * ks][1],     ph[0], pl[0]);
            hilo2(s[2 * ks][2],     s[2 * ks][3],     ph[1], pl[1]);
            hilo2(s[2 * ks + 1][0], s[2 * ks + 1][1], ph[2], pl[2]);
            hilo2(s[2 * ks + 1][2], s[2 * ks + 1][3], ph[3], pl[3]);
            #pragma unroll
            for (int j = 0; j < 4; j += 2) {
                uint32_t vh[2][4], vl[2][4];
                #pragma unroll
                for (int u = 0; u < 2; ++u) {
                    const uint32_t key = ks * 16 + ((lane >> 3) & 1) * 8 + (lane & 7);
                    const uint32_t blk = 2 * (j + u) + (lane >> 4);
                    const uint32_t off = key * 128 + ((blk ^ (key & 7)) * 16);
                    ldsm4t(vh[u], vH + off);
                    ldsm4t(vl[u], vL + off);
                }
                mma16816(o[2 * j],     ph, &vh[0][0]);
                mma16816(o[2 * j + 1], ph, &vh[0][2]);
                mma16816(o[2 * j + 2], ph, &vh[1][0]);
                mma16816(o[2 * j + 3], ph, &vh[1][2]);
                mma16816(o[2 * j],     ph, &vl[0][0]);
                mma16816(o[2 * j + 1], ph, &vl[0][2]);
                mma16816(o[2 * j + 2], ph, &vl[1][0]);
                mma16816(o[2 * j + 3], ph, &vl[1][2]);
                mma16816(o[2 * j],     pl, &vh[0][0]);
                mma16816(o[2 * j + 1], pl, &vh[0][2]);
                mma16816(o[2 * j + 2], pl, &vh[1][0]);
                mma16816(o[2 * j + 3], pl, &vh[1][2]);
            }
        }
    }

    const float inv0 = 1.0f / s_l0, inv1 = 1.0f / s_l1;
    const size_t row0 = (size_t)bt * NTOK + rb * 128 + w * 16 + g;
    const size_t row1 = row0 + 8;
    #pragma unroll
    for (int nf = 0; nf < 8; ++nf) {
        const int col = h * HD + nf * 8 + q2;
        uint32_t hh, ll;
        hilo2(o[nf][0] * inv0, o[nf][1] * inv0, hh, ll);
        *(uint32_t*)&g_attn_hi[row0 * DMODEL + col] = hh;
        *(uint32_t*)&g_attn_lo[row0 * DMODEL + col] = ll;
        hilo2(o[nf][2] * inv1, o[nf][3] * inv1, hh, ll);
        *(uint32_t*)&g_attn_hi[row1 * DMODEL + col] = hh;
        *(uint32_t*)&g_attn_lo[row1 * DMODEL + col] = ll;
    }
}

// ---------------------------------------------------------------------------
extern "C" void kernel_launch(void* const* d_in, const int* in_sizes, int n_in,
                              void* d_out, int out_size)
{
    const float* x      = (const float*)d_in[0];
    const float* W_qkv  = (const float*)d_in[1];
    const float* b_qkv  = (const float*)d_in[2];
    const float* W_proj = (const float*)d_in[3];
    const float* b_proj = (const float*)d_in[4];
    float* out = (float*)d_out;

    void *pqh, *pql, *pxh, *pxl, *pwqh, *pwql, *pwph, *pwpl, *pah, *pal;
    cudaGetSymbolAddress(&pqh, g_qkvh);    cudaGetSymbolAddress(&pql, g_qkvl);
    cudaGetSymbolAddress(&pxh, g_x_hi);    cudaGetSymbolAddress(&pxl, g_x_lo);
    cudaGetSymbolAddress(&pwqh, g_wqt_hi); cudaGetSymbolAddress(&pwql, g_wqt_lo);
    cudaGetSymbolAddress(&pwph, g_wpt_hi); cudaGetSymbolAddress(&pwpl, g_wpt_lo);
    cudaGetSymbolAddress(&pah, g_attn_hi); cudaGetSymbolAddress(&pal, g_attn_lo);

    cudaFuncSetAttribute(gemm_mma,
                         cudaFuncAttributeMaxDynamicSharedMemorySize, GEMM_SMEM);
    cudaFuncSetAttribute(flash_mma,
                         cudaFuncAttributeMaxDynamicSharedMemorySize, FLASH_SMEM);

    {
        const int n4 = MROWS * DMODEL / 4;
        cvt_hilo<<<(n4 + 255) / 256, 256>>>(x, (__nv_bfloat16*)pxh,
                                            (__nv_bfloat16*)pxl, n4);
    }
    {
        dim3 blk(32, 8);
        transpose_cvt<<<dim3(QKV_COLS / 32, DMODEL / 32), blk>>>(
            W_qkv, (__nv_bfloat16*)pwqh, (__nv_bfloat16*)pwql, DMODEL, QKV_COLS);
        transpose_cvt<<<dim3(DMODEL / 32, DMODEL / 32), blk>>>(
            W_proj, (__nv_bfloat16*)pwph, (__nv_bfloat16*)pwpl, DMODEL, DMODEL);
    }
    {
        dim3 grid(QKV_COLS / 128, MROWS / 128);
        gemm_mma<<<grid, 256, GEMM_SMEM>>>(
            (const __nv_bfloat16*)pxh, (const __nv_bfloat16*)pxl,
            (const __nv_bfloat16*)pwqh, (const __nv_bfloat16*)pwql,
            b_qkv, nullptr,
            (__nv_bfloat16*)pqh, (__nv_bfloat16*)pql, QKV_COLS);
    }
    {
        dim3 grid(NTOK / 128, BT_TOTAL * NHEADS);
        flash_mma<<<grid, 256, FLASH_SMEM>>>();
    }
    {
        dim3 grid(DMODEL / 128, MROWS / 128);
        gemm_mma<<<grid, 256, GEMM_SMEM>>>(
            (const __nv_bfloat16*)pah, (const __nv_bfloat16*)pal,
            (const __nv_bfloat16*)pwph, (const __nv_bfloat16*)pwpl,
            b_proj, out, nullptr, nullptr, DMODEL);
    }
}

// round 8
// speedup vs baseline: 1.1618x; 1.0777x over previous
#include <cuda_runtime.h>
#include <cuda_bf16.h>
#include <cstdint>

// ---------------------------------------------------------------------------
// SpatialAttention on GB300 (sm_103, mma.sync HMMA path)
// Round 8: gemm = 3-stage pipeline AND 2 CTAs/SM simultaneously.
// Dense conflict-free smem layout (row pairs packed into 128B lines with
// XOR-4 block swizzle) gives 32KB stages -> 96KB total -> 2 CTAs/SM, while
// depth-3 prefetch covers L2/DRAM latency. Warp tile 64x64 (4 warps/CTA).
// ---------------------------------------------------------------------------

#define BT_TOTAL 16
#define NTOK     1024
#define DMODEL   512
#define NHEADS   8
#define HD       64
#define MROWS    (BT_TOTAL * NTOK)      // 16384
#define QKV_COLS (3 * DMODEL)           // 1536
#define KDIM     512

__device__ __nv_bfloat16  g_qkvh[(size_t)MROWS * QKV_COLS];
__device__ __nv_bfloat16  g_qkvl[(size_t)MROWS * QKV_COLS];
__device__ __nv_bfloat16  g_x_hi[(size_t)MROWS * DMODEL];
__device__ __nv_bfloat16  g_x_lo[(size_t)MROWS * DMODEL];
__device__ __nv_bfloat16  g_wqt_hi[(size_t)QKV_COLS * DMODEL];
__device__ __nv_bfloat16  g_wqt_lo[(size_t)QKV_COLS * DMODEL];
__device__ __nv_bfloat16  g_wpt_hi[(size_t)DMODEL * DMODEL];
__device__ __nv_bfloat16  g_wpt_lo[(size_t)DMODEL * DMODEL];
__device__ __nv_bfloat16  g_attn_hi[(size_t)MROWS * DMODEL];
__device__ __nv_bfloat16  g_attn_lo[(size_t)MROWS * DMODEL];

// ---------------------------------------------------------------------------
// helpers
// ---------------------------------------------------------------------------
__device__ __forceinline__ uint32_t smem_u32(const void* p) {
    uint32_t a;
    asm("{ .reg .u64 t; cvta.to.shared.u64 t, %1; cvt.u32.u64 %0, t; }"
        : "=r"(a) : "l"(p));
    return a;
}
__device__ __forceinline__ void ldsm4(uint32_t* r, uint32_t a) {
    asm volatile("ldmatrix.sync.aligned.m8n8.x4.shared.b16 {%0,%1,%2,%3}, [%4];"
        : "=r"(r[0]), "=r"(r[1]), "=r"(r[2]), "=r"(r[3]) : "r"(a));
}
__device__ __forceinline__ void ldsm4t(uint32_t* r, uint32_t a) {
    asm volatile("ldmatrix.sync.aligned.m8n8.x4.trans.shared.b16 {%0,%1,%2,%3}, [%4];"
        : "=r"(r[0]), "=r"(r[1]), "=r"(r[2]), "=r"(r[3]) : "r"(a));
}
__device__ __forceinline__ void mma16816(float* d, const uint32_t* a, const uint32_t* b) {
    asm volatile("mma.sync.aligned.m16n8k16.row.col.f32.bf16.bf16.f32 "
        "{%0,%1,%2,%3},{%4,%5,%6,%7},{%8,%9},{%0,%1,%2,%3};"
        : "+f"(d[0]), "+f"(d[1]), "+f"(d[2]), "+f"(d[3])
        : "r"(a[0]), "r"(a[1]), "r"(a[2]), "r"(a[3]), "r"(b[0]), "r"(b[1]));
}
__device__ __forceinline__ void cp_async16(uint32_t s, const void* g) {
    asm volatile("cp.async.cg.shared.global [%0], [%1], 16;" :: "r"(s), "l"(g));
}
#define CP_COMMIT() asm volatile("cp.async.commit_group;")
#define CP_WAIT(n)  asm volatile("cp.async.wait_group %0;" :: "n"(n) : "memory")

__device__ __forceinline__ void hilo2(float a, float b, uint32_t& h, uint32_t& l) {
    __nv_bfloat162 hb = __floats2bfloat162_rn(a, b);
    float2 hf = __bfloat1622float2(hb);
    __nv_bfloat162 lb = __floats2bfloat162_rn(a - hf.x, b - hf.y);
    h = *(uint32_t*)&hb;
    l = *(uint32_t*)&lb;
}

// dense k32 tile layout: row pairs share a 128B line, XOR-4 block swizzle.
// addr(r, b) for r in [0,128), b in [0,4): all 8 16B bank-groups distinct
// across any 8 consecutive rows at fixed b -> LDSM/STS conflict-free.
__device__ __forceinline__ uint32_t tile_addr(uint32_t r, uint32_t b) {
    return (r >> 1) * 128 + (r & 1) * 64 + ((b ^ ((r >> 1) & 3)) * 16);
}

// ---------------------------------------------------------------------------
// prep kernels
// ---------------------------------------------------------------------------
__global__ void cvt_hilo(const float* __restrict__ X, __nv_bfloat16* __restrict__ H,
                         __nv_bfloat16* __restrict__ L, int n4)
{
    int i = blockIdx.x * blockDim.x + threadIdx.x;
    if (i >= n4) return;
    float4 v = ((const float4*)X)[i];
    uint32_t h0, l0, h1, l1;
    hilo2(v.x, v.y, h0, l0);
    hilo2(v.z, v.w, h1, l1);
    ((uint32_t*)H)[i * 2 + 0] = h0;
    ((uint32_t*)H)[i * 2 + 1] = h1;
    ((uint32_t*)L)[i * 2 + 0] = l0;
    ((uint32_t*)L)[i * 2 + 1] = l1;
}

__global__ void transpose_cvt(const float* __restrict__ W, __nv_bfloat16* __restrict__ Th,
                              __nv_bfloat16* __restrict__ Tl, int K, int N)
{
    __shared__ float tile[32][33];
    const int bx = blockIdx.x * 32;
    const int by = blockIdx.y * 32;
    const int tx = threadIdx.x, ty = threadIdx.y;
    #pragma unroll
    for (int i = 0; i < 32; i += 8)
        tile[ty + i][tx] = W[(size_t)(by + ty + i) * N + bx + tx];
    __syncthreads();
    #pragma unroll
    for (int i = 0; i < 32; i += 8) {
        float v = tile[tx][ty + i];
        size_t o = (size_t)(bx + ty + i) * K + by + tx;
        __nv_bfloat16 h = __float2bfloat16(v);
        Th[o] = h;
        Tl[o] = __float2bfloat16(v - __bfloat162float(h));
    }
}

// ---------------------------------------------------------------------------
// split-bf16 GEMM: CTA 128x128, 128 threads (4 warps 2x2, warp tile 64x64),
// k-chunk 32, 3-stage cp.async pipeline, dense 32KB stages => 96KB, 2 CTAs/SM.
// ---------------------------------------------------------------------------
#define G_T   8192                      // one matrix tile: 128 rows x 64B
#define GSTG  (4 * G_T)                 // Ah, Al, Bh, Bl = 32768
#define GEMM_SMEM (3 * GSTG)            // 98304

__global__ __launch_bounds__(128, 2)
void gemm_mma(const __nv_bfloat16* __restrict__ Ah, const __nv_bfloat16* __restrict__ Al,
              const __nv_bfloat16* __restrict__ Bh, const __nv_bfloat16* __restrict__ Bl,
              const float* __restrict__ bias, float* __restrict__ Cf,
              __nv_bfloat16* __restrict__ Chi, __nv_bfloat16* __restrict__ Clo, int Ntot)
{
    extern __shared__ char sm[];
    const uint32_t sb = smem_u32(sm);
    const int t = threadIdx.x, lane = t & 31, w = t >> 5;
    const int wm = w >> 1, wn = w & 1;          // 2 x 2 warps, 64x64 tiles
    const int bm = blockIdx.y * 128, bn = blockIdx.x * 128;

    // loader tasks: 512 (row, blk) pairs per matrix, 4 per thread
    const __nv_bfloat16* pA_[4][2];
    const __nv_bfloat16* pB_[4][2];
    uint32_t dst_[4];
    #pragma unroll
    for (int i = 0; i < 4; ++i) {
        const int idx = t + i * 128;
        const int row = idx >> 2, blk = idx & 3;
        pA_[i][0] = Ah + (size_t)(bm + row) * KDIM + blk * 8;
        pA_[i][1] = Al + (size_t)(bm + row) * KDIM + blk * 8;
        pB_[i][0] = Bh + (size_t)(bn + row) * KDIM + blk * 8;
        pB_[i][1] = Bl + (size_t)(bn + row) * KDIM + blk * 8;
        dst_[i] = tile_addr(row, blk);
    }

    float acc[4][8][4];
    #pragma unroll
    for (int a = 0; a < 4; ++a)
        #pragma unroll
        for (int b = 0; b < 8; ++b)
            #pragma unroll
            for (int c = 0; c < 4; ++c) acc[a][b][c] = 0.f;

    // prologue: chunks 0,1 into stages 0,1
    #pragma unroll
    for (int c = 0; c < 2; ++c) {
        const int koff = c * 32;
        const uint32_t st = sb + c * GSTG;
        #pragma unroll
        for (int i = 0; i < 4; ++i) {
            cp_async16(st + dst_[i],           pA_[i][0] + koff);
            cp_async16(st + G_T + dst_[i],     pA_[i][1] + koff);
            cp_async16(st + 2 * G_T + dst_[i], pB_[i][0] + koff);
            cp_async16(st + 3 * G_T + dst_[i], pB_[i][1] + koff);
        }
        CP_COMMIT();
    }

    int stg = 0;            // stage holding chunk c
    int nstg = 2;           // stage to fill with chunk c+2
    for (int c = 0; c < 16; ++c) {
        if (c < 14) CP_WAIT(1); else CP_WAIT(0);
        __syncthreads();

        if (c + 2 < 16) {
            const int koff = (c + 2) * 32;
            const uint32_t st = sb + nstg * GSTG;
            #pragma unroll
            for (int i = 0; i < 4; ++i) {
                cp_async16(st + dst_[i],           pA_[i][0] + koff);
                cp_async16(st + G_T + dst_[i],     pA_[i][1] + koff);
                cp_async16(st + 2 * G_T + dst_[i], pB_[i][0] + koff);
                cp_async16(st + 3 * G_T + dst_[i], pB_[i][1] + koff);
            }
            CP_COMMIT();
        }

        const uint32_t aH = sb + stg * GSTG;
        const uint32_t aL = aH + G_T;
        const uint32_t bH = aH + 2 * G_T;
        const uint32_t bL = aH + 3 * G_T;

        #pragma unroll
        for (int ks = 0; ks < 2; ++ks) {
            const uint32_t blkA = 2 * ks + (lane >> 4);
            const uint32_t blkB = 2 * ks + ((lane >> 3) & 1);
            const uint32_t rbase = wm * 64 + ((lane >> 3) & 1) * 8 + (lane & 7);
            const uint32_t nbase = wn * 64 + (lane >> 4) * 8 + (lane & 7);

            uint32_t bh[4][4], bl[4][4], ah[4][4];
            #pragma unroll
            for (int j = 0; j < 4; ++j) {
                const uint32_t off = tile_addr(nbase + j * 16, blkB);
                ldsm4(bh[j], bH + off);
                ldsm4(bl[j], bL + off);
            }
            #pragma unroll
            for (int mf = 0; mf < 4; ++mf)
                ldsm4(ah[mf], aH + tile_addr(rbase + mf * 16, blkA));

            // pass 1: hi*hi (32 independent)
            #pragma unroll
            for (int mf = 0; mf < 4; ++mf)
                #pragma unroll
                for (int nf = 0; nf < 8; ++nf)
                    mma16816(acc[mf][nf], ah[mf], &bh[nf >> 1][(nf & 1) * 2]);
            // pass 2: hi*lo
            #pragma unroll
            for (int mf = 0; mf < 4; ++mf)
                #pragma unroll
                for (int nf = 0; nf < 8; ++nf)
                    mma16816(acc[mf][nf], ah[mf], &bl[nf >> 1][(nf & 1) * 2]);
            // pass 3: lo*hi (al streamed per mf)
            #pragma unroll
            for (int mf = 0; mf < 4; ++mf) {
                uint32_t al[4];
                ldsm4(al, aL + tile_addr(rbase + mf * 16, blkA));
                #pragma unroll
                for (int nf = 0; nf < 8; ++nf)
                    mma16816(acc[mf][nf], al, &bh[nf >> 1][(nf & 1) * 2]);
            }
        }
        stg = (stg == 2) ? 0 : stg + 1;
        nstg = (nstg == 2) ? 0 : nstg + 1;
    }

    const int g = lane >> 2, q2 = (lane & 3) * 2;
    #pragma unroll
    for (int mf = 0; mf < 4; ++mf) {
        const int r0 = bm + wm * 64 + mf * 16 + g;
        #pragma unroll
        for (int nf = 0; nf < 8; ++nf) {
            const int col = bn + wn * 64 + nf * 8 + q2;
            const float b0 = bias[col], b1 = bias[col + 1];
            const float v00 = acc[mf][nf][0] + b0, v01 = acc[mf][nf][1] + b1;
            const float v10 = acc[mf][nf][2] + b0, v11 = acc[mf][nf][3] + b1;
            if (Chi) {
                uint32_t hh, ll;
                hilo2(v00, v01, hh, ll);
                *(uint32_t*)&Chi[(size_t)r0 * Ntot + col] = hh;
                *(uint32_t*)&Clo[(size_t)r0 * Ntot + col] = ll;
                hilo2(v10, v11, hh, ll);
                *(uint32_t*)&Chi[(size_t)(r0 + 8) * Ntot + col] = hh;
                *(uint32_t*)&Clo[(size_t)(r0 + 8) * Ntot + col] = ll;
            } else {
                *(float2*)&Cf[(size_t)r0 * Ntot + col]       = make_float2(v00, v01);
                *(float2*)&Cf[(size_t)(r0 + 8) * Ntot + col] = make_float2(v10, v11);
            }
        }
    }
}

// ---------------------------------------------------------------------------
// Flash attention (unchanged from R7): bf16 hi/lo cp.async, double-buffered
// KV, fragment softmax, pass-separated MMA triples. 2 CTAs/SM.
// ---------------------------------------------------------------------------
#define FQ_H 0
#define FQ_L 16384
#define FKV0 32768
#define FKV_STG 32768
#define FLASH_SMEM 98304

__global__ __launch_bounds__(256, 2)
void flash_mma()
{
    const int rb = blockIdx.x;
    const int pp = blockIdx.y;
    const int bt = pp >> 3, h = pp & 7;
    extern __shared__ char sm[];
    const uint32_t sb = smem_u32(sm);
    const int t = threadIdx.x, lane = t & 31, w = t >> 5;
    const size_t base = (size_t)bt * NTOK * QKV_COLS;

    const int lrow0 = t >> 3,         lblk0 = t & 7;
    const int lrow1 = (t + 256) >> 3, lblk1 = (t + 256) & 7;
    const uint32_t kvd0 = (uint32_t)(lrow0 * 128 + ((lblk0 ^ (lrow0 & 7)) * 16));
    const uint32_t kvd1 = (uint32_t)(lrow1 * 128 + ((lblk1 ^ (lrow1 & 7)) * 16));

    {
        #pragma unroll
        for (int i = 0; i < 4; ++i) {
            const int idx = t + i * 256;
            const int row = idx >> 3, blk = idx & 7;
            const uint32_t d = (uint32_t)(row * 128 + ((blk ^ (row & 7)) * 16));
            const size_t src = base + (size_t)(rb * 128 + row) * QKV_COLS + h * HD + blk * 8;
            cp_async16(sb + FQ_H + d, g_qkvh + src);
            cp_async16(sb + FQ_L + d, g_qkvl + src);
        }
        const size_t k0 = base + (size_t)lrow0 * QKV_COLS + DMODEL + h * HD + lblk0 * 8;
        const size_t k1 = base + (size_t)lrow1 * QKV_COLS + DMODEL + h * HD + lblk1 * 8;
        const uint32_t st = sb + FKV0;
        cp_async16(st + kvd0,         g_qkvh + k0);
        cp_async16(st + kvd1,         g_qkvh + k1);
        cp_async16(st + 8192 + kvd0,  g_qkvl + k0);
        cp_async16(st + 8192 + kvd1,  g_qkvl + k1);
        cp_async16(st + 16384 + kvd0, g_qkvh + k0 + DMODEL);
        cp_async16(st + 16384 + kvd1, g_qkvh + k1 + DMODEL);
        cp_async16(st + 24576 + kvd0, g_qkvl + k0 + DMODEL);
        cp_async16(st + 24576 + kvd1, g_qkvl + k1 + DMODEL);
        CP_COMMIT();
    }

    float s_m0 = -1e30f, s_m1 = -1e30f, s_l0 = 0.f, s_l1 = 0.f;
    float o[8][4];
    #pragma unroll
    for (int nf = 0; nf < 8; ++nf)
        #pragma unroll
        for (int i = 0; i < 4; ++i) o[nf][i] = 0.f;

    const int g = lane >> 2, q2 = (lane & 3) * 2;
    const float SC = 0.125f;

    for (int kb = 0; kb < 16; ++kb) {
        CP_WAIT(0);
        __syncthreads();

        if (kb + 1 < 16) {
            const int r = (kb + 1) * 64;
            const size_t k0 = base + (size_t)(r + lrow0) * QKV_COLS + DMODEL + h * HD + lblk0 * 8;
            const size_t k1 = base + (size_t)(r + lrow1) * QKV_COLS + DMODEL + h * HD + lblk1 * 8;
            const uint32_t st = sb + FKV0 + ((kb + 1) & 1) * FKV_STG;
            cp_async16(st + kvd0,         g_qkvh + k0);
            cp_async16(st + kvd1,         g_qkvh + k1);
            cp_async16(st + 8192 + kvd0,  g_qkvl + k0);
            cp_async16(st + 8192 + kvd1,  g_qkvl + k1);
            cp_async16(st + 16384 + kvd0, g_qkvh + k0 + DMODEL);
            cp_async16(st + 16384 + kvd1, g_qkvh + k1 + DMODEL);
            cp_async16(st + 24576 + kvd0, g_qkvl + k0 + DMODEL);
            cp_async16(st + 24576 + kvd1, g_qkvl + k1 + DMODEL);
            CP_COMMIT();
        }

        const uint32_t kH = sb + FKV0 + (kb & 1) * FKV_STG;
        const uint32_t kL = kH + 8192;
        const uint32_t vH = kH + 16384;
        const uint32_t vL = kH + 24576;

        float s[8][4];
        #pragma unroll
        for (int nf = 0; nf < 8; ++nf)
            #pragma unroll
            for (int i = 0; i < 4; ++i) s[nf][i] = 0.f;

        #pragma unroll
        for (int ks = 0; ks < 4; ++ks) {
            uint32_t ah[4], al[4];
            {
                const uint32_t r   = w * 16 + ((lane >> 3) & 1) * 8 + (lane & 7);
                const uint32_t blk = 2 * ks + (lane >> 4);
                const uint32_t off = r * 128 + ((blk ^ (r & 7)) * 16);
                ldsm4(ah, sb + FQ_H + off);
                ldsm4(al, sb + FQ_L + off);
            }
            #pragma unroll
            for (int j = 0; j < 4; j += 2) {
                uint32_t bh[2][4], bl[2][4];
                #pragma unroll
                for (int u = 0; u < 2; ++u) {
                    const uint32_t key = (j + u) * 16 + (lane >> 4) * 8 + (lane & 7);
                    const uint32_t blk = 2 * ks + ((lane >> 3) & 1);
                    const uint32_t off = key * 128 + ((blk ^ (key & 7)) * 16);
                    ldsm4(bh[u], kH + off);
                    ldsm4(bl[u], kL + off);
                }
                mma16816(s[2 * j],     ah, &bh[0][0]);
                mma16816(s[2 * j + 1], ah, &bh[0][2]);
                mma16816(s[2 * j + 2], ah, &bh[1][0]);
                mma16816(s[2 * j + 3], ah, &bh[1][2]);
                mma16816(s[2 * j],     ah, &bl[0][0]);
                mma16816(s[2 * j + 1], ah, &bl[0][2]);
                mma16816(s[2 * j + 2], ah, &bl[1][0]);
                mma16816(s[2 * j + 3], ah, &bl[1][2]);
                mma16816(s[2 * j],     al, &bh[0][0]);
                mma16816(s[2 * j + 1], al, &bh[0][2]);
                mma16816(s[2 * j + 2], al, &bh[1][0]);
                mma16816(s[2 * j + 3], al, &bh[1][2]);
            }
        }

        float mt0 = -1e30f, mt1 = -1e30f;
        #pragma unroll
        for (int nf = 0; nf < 8; ++nf) {
            mt0 = fmaxf(mt0, fmaxf(s[nf][0], s[nf][1]));
            mt1 = fmaxf(mt1, fmaxf(s[nf][2], s[nf][3]));
        }
        mt0 = fmaxf(mt0, __shfl_xor_sync(0xffffffffu, mt0, 1));
        mt0 = fmaxf(mt0, __shfl_xor_sync(0xffffffffu, mt0, 2));
        mt1 = fmaxf(mt1, __shfl_xor_sync(0xffffffffu, mt1, 1));
        mt1 = fmaxf(mt1, __shfl_xor_sync(0xffffffffu, mt1, 2));

        const float mn0 = fmaxf(s_m0, mt0), mn1 = fmaxf(s_m1, mt1);
        const float c0 = __expf((s_m0 - mn0) * SC), c1 = __expf((s_m1 - mn1) * SC);
        s_m0 = mn0; s_m1 = mn1;
        const float mo0 = mn0 * SC, mo1 = mn1 * SC;

        float ps0 = 0.f, ps1 = 0.f;
        #pragma unroll
        for (int nf = 0; nf < 8; ++nf) {
            s[nf][0] = __expf(fmaf(s[nf][0], SC, -mo0));
            s[nf][1] = __expf(fmaf(s[nf][1], SC, -mo0));
            s[nf][2] = __expf(fmaf(s[nf][2], SC, -mo1));
            s[nf][3] = __expf(fmaf(s[nf][3], SC, -mo1));
            ps0 += s[nf][0] + s[nf][1];
            ps1 += s[nf][2] + s[nf][3];
        }
        ps0 += __shfl_xor_sync(0xffffffffu, ps0, 1);
        ps0 += __shfl_xor_sync(0xffffffffu, ps0, 2);
        ps1 += __shfl_xor_sync(0xffffffffu, ps1, 1);
        ps1 += __shfl_xor_sync(0xffffffffu, ps1, 2);
        s_l0 = s_l0 * c0 + ps0;
        s_l1 = s_l1 * c1 + ps1;

        #pragma unroll
        for (int nf = 0; nf < 8; ++nf) {
            o[nf][0] *= c0; o[nf][1] *= c0;
            o[nf][2] *= c1; o[nf][3] *= c1;
        }

        #pragma unroll
        for (int ks = 0; ks < 4; ++ks) {
            uint32_t ph[4], pl[4];
            hilo2(s[2 * ks][0],     s[2 * ks][1],     ph[0], pl[0]);
            hilo2(s[2 * ks][2],     s[2 * ks][3],     ph[1], pl[1]);
            hilo2(s[2 * ks + 1][0], s[2 * ks + 1][1], ph[2], pl[2]);
            hilo2(s[2 * ks + 1][2], s[2 * ks + 1][3], ph[3], pl[3]);
            #pragma unroll
            for (int j = 0; j < 4; j += 2) {
                uint32_t vh[2][4], vl[2][4];
                #pragma unroll
                for (int u = 0; u < 2; ++u) {
                    const uint32_t key = ks * 16 + ((lane >> 3) & 1) * 8 + (lane & 7);
                    const uint32_t blk = 2 * (j + u) + (lane >> 4);
                    const uint32_t off = key * 128 + ((blk ^ (key & 7)) * 16);
                    ldsm4t(vh[u], vH + off);
                    ldsm4t(vl[u], vL + off);
                }
                mma16816(o[2 * j],     ph, &vh[0][0]);
                mma16816(o[2 * j + 1], ph, &vh[0][2]);
                mma16816(o[2 * j + 2], ph, &vh[1][0]);
                mma16816(o[2 * j + 3], ph, &vh[1][2]);
                mma16816(o[2 * j],     ph, &vl[0][0]);
                mma16816(o[2 * j + 1], ph, &vl[0][2]);
                mma16816(o[2 * j + 2], ph, &vl[1][0]);
                mma16816(o[2 * j + 3], ph, &vl[1][2]);
                mma16816(o[2 * j],     pl, &vh[0][0]);
                mma16816(o[2 * j + 1], pl, &vh[0][2]);
                mma16816(o[2 * j + 2], pl, &vh[1][0]);
                mma16816(o[2 * j + 3], pl, &vh[1][2]);
            }
        }
    }

    const float inv0 = 1.0f / s_l0, inv1 = 1.0f / s_l1;
    const size_t row0 = (size_t)bt * NTOK + rb * 128 + w * 16 + g;
    const size_t row1 = row0 + 8;
    #pragma unroll
    for (int nf = 0; nf < 8; ++nf) {
        const int col = h * HD + nf * 8 + q2;
        uint32_t hh, ll;
        hilo2(o[nf][0] * inv0, o[nf][1] * inv0, hh, ll);
        *(uint32_t*)&g_attn_hi[row0 * DMODEL + col] = hh;
        *(uint32_t*)&g_attn_lo[row0 * DMODEL + col] = ll;
        hilo2(o[nf][2] * inv1, o[nf][3] * inv1, hh, ll);
        *(uint32_t*)&g_attn_hi[row1 * DMODEL + col] = hh;
        *(uint32_t*)&g_attn_lo[row1 * DMODEL + col] = ll;
    }
}

// ---------------------------------------------------------------------------
extern "C" void kernel_launch(void* const* d_in, const int* in_sizes, int n_in,
                              void* d_out, int out_size)
{
    const float* x      = (const float*)d_in[0];
    const float* W_qkv  = (const float*)d_in[1];
    const float* b_qkv  = (const float*)d_in[2];
    const float* W_proj = (const float*)d_in[3];
    const float* b_proj = (const float*)d_in[4];
    float* out = (float*)d_out;

    void *pqh, *pql, *pxh, *pxl, *pwqh, *pwql, *pwph, *pwpl, *pah, *pal;
    cudaGetSymbolAddress(&pqh, g_qkvh);    cudaGetSymbolAddress(&pql, g_qkvl);
    cudaGetSymbolAddress(&pxh, g_x_hi);    cudaGetSymbolAddress(&pxl, g_x_lo);
    cudaGetSymbolAddress(&pwqh, g_wqt_hi); cudaGetSymbolAddress(&pwql, g_wqt_lo);
    cudaGetSymbolAddress(&pwph, g_wpt_hi); cudaGetSymbolAddress(&pwpl, g_wpt_lo);
    cudaGetSymbolAddress(&pah, g_attn_hi); cudaGetSymbolAddress(&pal, g_attn_lo);

    cudaFuncSetAttribute(gemm_mma,
                         cudaFuncAttributeMaxDynamicSharedMemorySize, GEMM_SMEM);
    cudaFuncSetAttribute(flash_mma,
                         cudaFuncAttributeMaxDynamicSharedMemorySize, FLASH_SMEM);

    {
        const int n4 = MROWS * DMODEL / 4;
        cvt_hilo<<<(n4 + 255) / 256, 256>>>(x, (__nv_bfloat16*)pxh,
                                            (__nv_bfloat16*)pxl, n4);
    }
    {
        dim3 blk(32, 8);
        transpose_cvt<<<dim3(QKV_COLS / 32, DMODEL / 32), blk>>>(
            W_qkv, (__nv_bfloat16*)pwqh, (__nv_bfloat16*)pwql, DMODEL, QKV_COLS);
        transpose_cvt<<<dim3(DMODEL / 32, DMODEL / 32), blk>>>(
            W_proj, (__nv_bfloat16*)pwph, (__nv_bfloat16*)pwpl, DMODEL, DMODEL);
    }
    {
        dim3 grid(QKV_COLS / 128, MROWS / 128);
        gemm_mma<<<grid, 128, GEMM_SMEM>>>(
            (const __nv_bfloat16*)pxh, (const __nv_bfloat16*)pxl,
            (const __nv_bfloat16*)pwqh, (const __nv_bfloat16*)pwql,
            b_qkv, nullptr,
            (__nv_bfloat16*)pqh, (__nv_bfloat16*)pql, QKV_COLS);
    }
    {
        dim3 grid(NTOK / 128, BT_TOTAL * NHEADS);
        flash_mma<<<grid, 256, FLASH_SMEM>>>();
    }
    {
        dim3 grid(DMODEL / 128, MROWS / 128);
        gemm_mma<<<grid, 128, GEMM_SMEM>>>(
            (const __nv_bfloat16*)pah, (const __nv_bfloat16*)pal,
            (const __nv_bfloat16*)pwph, (const __nv_bfloat16*)pwpl,
            b_proj, out, nullptr, nullptr, DMODEL);
    }
}